// round 9
// baseline (speedup 1.0000x reference)
#include <cuda_runtime.h>
#include <cuda_bf16.h>

// Cutout: out = x with a 16x16 box (centered at (cy[b], cx[b])) zeroed per image.
// x: [B=256, C=3, H=224, W=224] fp32 contiguous. cy, cx: [1,256] int32.
//
// Best-measured config (R2: unroll x4, warp-coalesced, 64-image stride so all
// sub-elements share (c,h,w)) + exact grid (no bounds check) + streaming
// cache hints + 512-thread blocks. MLP=4 @ ~32 regs keeps occupancy ~80%,
// which the R1/R2/R8 sweep showed is the DRAM%-optimal balance.

#define B 256
#define C 3
#define H 224
#define W 224
#define HALF 8

#define W4     (W / 4)            // 56
#define HW4    (H * W4)           // 12544
#define CHW4   (C * HW4)          // 37632
#define TOTAL4 (B * CHW4)         // 9,633,792
#define UNROLL 4
#define CHUNK  (TOTAL4 / UNROLL)  // 2,408,448 == 64 * CHW4 (b advances by 64)
#define NTHR   512
#define NBLK   (CHUNK / NTHR)     // 4704 (exact: 4704*512 = 2,408,448)

__global__ void __launch_bounds__(NTHR) cutout_kernel(
    const float4* __restrict__ x,
    const int*    __restrict__ cy,
    const int*    __restrict__ cx,
    float4*       __restrict__ out)
{
    int i = blockIdx.x * NTHR + threadIdx.x;   // exact grid, no bounds check

    // Decompose once: i -> (b0, h, w). Sub-element j: b_j = b0 + 64*j, same (c,h,w).
    int b0   = i / CHW4;              // 0..63
    int rem  = i - b0 * CHW4;
    int hw4  = rem % HW4;
    int h    = hw4 / W4;
    int w    = (hw4 - h * W4) * 4;    // first of 4 consecutive W-coords

    // Front-batch 4 independent warp-coalesced 128-bit streaming loads (MLP=4).
    float4 v0 = __ldcs(x + i + 0 * CHUNK);
    float4 v1 = __ldcs(x + i + 1 * CHUNK);
    float4 v2 = __ldcs(x + i + 2 * CHUNK);
    float4 v3 = __ldcs(x + i + 3 * CHUNK);

    #define APPLY(v, j)                                                     \
        {                                                                   \
            int yc = __ldg(&cy[b0 + 64 * (j)]);                             \
            if (h >= yc - HALF && h < yc + HALF) {                          \
                int xc = __ldg(&cx[b0 + 64 * (j)]);                         \
                int x0 = xc - HALF, x1 = xc + HALF;                         \
                if (w + 0 >= x0 && w + 0 < x1) (v).x = 0.0f;                \
                if (w + 1 >= x0 && w + 1 < x1) (v).y = 0.0f;                \
                if (w + 2 >= x0 && w + 2 < x1) (v).z = 0.0f;                \
                if (w + 3 >= x0 && w + 3 < x1) (v).w = 0.0f;                \
            }                                                               \
        }

    APPLY(v0, 0);
    APPLY(v1, 1);
    APPLY(v2, 2);
    APPLY(v3, 3);
    #undef APPLY

    __stcs(out + i + 0 * CHUNK, v0);
    __stcs(out + i + 1 * CHUNK, v1);
    __stcs(out + i + 2 * CHUNK, v2);
    __stcs(out + i + 3 * CHUNK, v3);
}

extern "C" void kernel_launch(void* const* d_in, const int* in_sizes, int n_in,
                              void* d_out, int out_size)
{
    const float4* x   = (const float4*)d_in[0];
    const int*    cy  = (const int*)   d_in[1];
    const int*    cx  = (const int*)   d_in[2];
    float4*       out = (float4*)d_out;

    cutout_kernel<<<NBLK, NTHR>>>(x, cy, cx, out);
}